// round 4
// baseline (speedup 1.0000x reference)
#include <cuda_runtime.h>
#include <cstdint>

#define LEAKY 0.2f
#define B_ 4
#define H_ 4
#define N_ 4096
#define F_ 64
#define U_ 32
#define BH_ (B_*H_)
#define NC8 (N_/8)   // 512 chunks of 8 per (b,h)

// ---------------- scratch (device globals; no allocations) ----------------
__device__ float g_feats[BH_ * N_ * U_];   // [bh][n][u]
__device__ float g_s[BH_ * N_];            // a_self (original order)
__device__ float g_t[BH_ * N_];            // a_neigh (original order)
__device__ float g_ts[BH_ * N_];           // sorted t
__device__ int   g_perm[BH_ * N_];         // sorted -> original index
__device__ float g_w1[BH_ * N_];           // exp(t) sorted order
__device__ float g_w2[BH_ * N_];           // exp(alpha*t) sorted order
__device__ float g_S1[BH_ * N_];           // inclusive scalar prefix of w1 (sorted)
__device__ float g_S2[BH_ * N_];
__device__ float g_T1[BH_ * NC8 * U_];     // 8-chunk totals of w1*feats
__device__ float g_T2[BH_ * NC8 * U_];
__device__ float g_O1[BH_ * NC8 * U_];     // exclusive chunk offsets
__device__ float g_O2[BH_ * NC8 * U_];
__device__ float g_Ptot1[BH_ * U_];        // grand totals of w1*feats

// ============================================================
// k1: feats = x@K per head; s,t projections.
// grid (N/128, BH), block 128
// ============================================================
__global__ void k1_feats(const float* __restrict__ x,
                         const float* __restrict__ kern,
                         const float* __restrict__ att_s,
                         const float* __restrict__ att_n) {
    __shared__ float  xs[128][F_ + 1];
    __shared__ float4 ks4[F_ * (U_ / 4)];
    __shared__ float  as_s[U_], as_n[U_];

    const int bh = blockIdx.y;
    const int b = bh / H_, h = bh % H_;
    const int tid = threadIdx.x;

    const float4* ksrc = (const float4*)(kern + (size_t)h * F_ * U_);
    for (int i = tid; i < F_ * (U_ / 4); i += 128) ks4[i] = ksrc[i];
    if (tid < U_) { as_s[tid] = att_s[h * U_ + tid]; as_n[tid] = att_n[h * U_ + tid]; }

    const int n0 = blockIdx.x * 128;
    const float* xb = x + ((size_t)b * N_ + n0) * F_;
    for (int i = tid; i < 128 * F_; i += 128) xs[i >> 6][i & 63] = xb[i];
    __syncthreads();

    float acc[U_];
#pragma unroll
    for (int u = 0; u < U_; u++) acc[u] = 0.f;

#pragma unroll 4
    for (int f = 0; f < F_; f++) {
        const float xv = xs[tid][f];
#pragma unroll
        for (int u4 = 0; u4 < U_ / 4; u4++) {
            const float4 kv = ks4[f * (U_ / 4) + u4];
            acc[u4 * 4 + 0] += xv * kv.x;
            acc[u4 * 4 + 1] += xv * kv.y;
            acc[u4 * 4 + 2] += xv * kv.z;
            acc[u4 * 4 + 3] += xv * kv.w;
        }
    }

    const int n = n0 + tid;
    float* fo = g_feats + ((size_t)bh * N_ + n) * U_;
#pragma unroll
    for (int u4 = 0; u4 < U_ / 4; u4++) {
        ((float4*)fo)[u4] = make_float4(acc[u4*4], acc[u4*4+1], acc[u4*4+2], acc[u4*4+3]);
    }
    float s = 0.f, t = 0.f;
#pragma unroll
    for (int u = 0; u < U_; u++) { s += acc[u] * as_s[u]; t += acc[u] * as_n[u]; }
    g_s[bh * N_ + n] = s;
    g_t[bh * N_ + n] = t;
}

// ============================================================
// k2: per-(b,h) bitonic sort of 4096 packed (key<<32 | idx).
// Register/shfl bitonic: thread owns 4 elements; j<=2 in-register,
// j=4..64 via shfl_xor, j>=128 via smem. Then exp + scalar scans
// computed directly on sorted values (no gathers).
// grid BH, block 1024   [identical to the verified 79.9us version]
// ============================================================
__device__ __forceinline__ void cmpswap_ull(unsigned long long& a,
                                            unsigned long long& b, bool asc) {
    if ((a > b) == asc) { unsigned long long t = a; a = b; b = t; }
}

__global__ void k2_sort_scan() {
    __shared__ unsigned long long sm[N_];
    __shared__ float w1s[32], w2s[32];

    const int bh = blockIdx.x;
    const int tid = threadIdx.x;
    const int lane = tid & 31, wid = tid >> 5;
    const int base = tid * 4;

    unsigned long long v[4];
#pragma unroll
    for (int e = 0; e < 4; e++) {
        const int i = base + e;
        unsigned int f = __float_as_uint(g_t[bh * N_ + i]);
        unsigned int u = (f & 0x80000000u) ? ~f : (f ^ 0x80000000u); // sortable
        v[e] = ((unsigned long long)u << 32) | (unsigned int)i;
    }

    cmpswap_ull(v[0], v[1], true);
    cmpswap_ull(v[2], v[3], false);

#pragma unroll
    for (int k = 4; k <= 128; k <<= 1) {
        const bool dir = ((base & k) == 0);
#pragma unroll
        for (int j = 64; j >= 4; j >>= 1) {
            if (j <= (k >> 1)) {
                const int lj = j >> 2;
                const bool takeMin = (((lane & lj) == 0) == dir);
#pragma unroll
                for (int e = 0; e < 4; e++) {
                    unsigned long long other = __shfl_xor_sync(0xffffffffu, v[e], lj);
                    v[e] = ((v[e] < other) == takeMin) ? v[e] : other;
                }
            }
        }
        cmpswap_ull(v[0], v[2], dir); cmpswap_ull(v[1], v[3], dir);
        cmpswap_ull(v[0], v[1], dir); cmpswap_ull(v[2], v[3], dir);
    }

    for (int k = 256; k <= N_; k <<= 1) {
#pragma unroll
        for (int e = 0; e < 4; e++) sm[base + e] = v[e];
        __syncthreads();
        for (int j = k >> 1; j >= 128; j >>= 1) {
#pragma unroll
            for (int r = 0; r < N_ / 1024; r++) {
                const int i = tid + r * 1024;
                const int ixj = i ^ j;
                if (ixj > i) {
                    const unsigned long long a = sm[i], c = sm[ixj];
                    const bool up = ((i & k) == 0);
                    if ((a > c) == up) { sm[i] = c; sm[ixj] = a; }
                }
            }
            __syncthreads();
        }
#pragma unroll
        for (int e = 0; e < 4; e++) v[e] = sm[base + e];
        const bool dir = ((base & k) == 0);
#pragma unroll
        for (int j = 64; j >= 4; j >>= 1) {
            const int lj = j >> 2;
            const bool takeMin = (((lane & lj) == 0) == dir);
#pragma unroll
            for (int e = 0; e < 4; e++) {
                unsigned long long other = __shfl_xor_sync(0xffffffffu, v[e], lj);
                v[e] = ((v[e] < other) == takeMin) ? v[e] : other;
            }
        }
        cmpswap_ull(v[0], v[2], dir); cmpswap_ull(v[1], v[3], dir);
        cmpswap_ull(v[0], v[1], dir); cmpswap_ull(v[2], v[3], dir);
    }

    // unpack sorted data (in regs), compute exp in place, scalar scans
    float l1[4], l2[4];
    float r1 = 0.f, r2 = 0.f;
#pragma unroll
    for (int i = 0; i < 4; i++) {
        const unsigned long long p = v[i];
        const unsigned int uk = (unsigned int)(p >> 32);
        const unsigned int f = (uk & 0x80000000u) ? (uk ^ 0x80000000u) : ~uk;
        const float tv = __uint_as_float(f);
        const int src = (int)(p & 0xffffffffu);
        g_ts[bh * N_ + base + i] = tv;
        g_perm[bh * N_ + base + i] = src;
        const float w1 = expf(tv);
        const float w2 = expf(LEAKY * tv);
        g_w1[bh * N_ + base + i] = w1;
        g_w2[bh * N_ + base + i] = w2;
        r1 += w1; r2 += w2;
        l1[i] = r1; l2[i] = r2;
    }
    float t1 = r1, t2 = r2;
#pragma unroll
    for (int off = 1; off < 32; off <<= 1) {
        const float a = __shfl_up_sync(0xffffffffu, t1, off);
        const float c = __shfl_up_sync(0xffffffffu, t2, off);
        if (lane >= off) { t1 += a; t2 += c; }
    }
    if (lane == 31) { w1s[wid] = t1; w2s[wid] = t2; }
    __syncthreads();
    if (wid == 0) {
        float a1 = w1s[lane], a2 = w2s[lane];
        float s1 = a1, s2 = a2;
#pragma unroll
        for (int off = 1; off < 32; off <<= 1) {
            const float x1 = __shfl_up_sync(0xffffffffu, s1, off);
            const float x2 = __shfl_up_sync(0xffffffffu, s2, off);
            if (lane >= off) { s1 += x1; s2 += x2; }
        }
        w1s[lane] = s1 - a1;
        w2s[lane] = s2 - a2;
    }
    __syncthreads();
    const float base1 = (t1 - r1) + w1s[wid];
    const float base2 = (t2 - r2) + w2s[wid];
#pragma unroll
    for (int i = 0; i < 4; i++) {
        g_S1[bh * N_ + base + i] = l1[i] + base1;
        g_S2[bh * N_ + base + i] = l2[i] + base2;
    }
}

// ============================================================
// k3t: 8-chunk totals of w*feats (gathered by perm). No dense prefixes.
// grid (BH, 32), block 256 = 8 warps; warp -> 16 sorted positions
// (= 2 chunks of 8), lane -> u.
// ============================================================
__global__ void k3t_chunk_totals() {
    const int bh = blockIdx.x;
    const int w = threadIdx.x >> 5, lane = threadIdx.x & 31;
    const int j0 = blockIdx.y * 128 + w * 16;

    const float* fe = g_feats + (size_t)bh * N_ * U_;
    const int c8 = j0 >> 3;

    float a1 = 0.f, a2 = 0.f;
#pragma unroll
    for (int i = 0; i < 8; i++) {
        const int jj = j0 + i;
        const int p = __ldg(&g_perm[bh * N_ + jj]);
        const float w1 = __ldg(&g_w1[bh * N_ + jj]);
        const float w2 = __ldg(&g_w2[bh * N_ + jj]);
        const float v = __ldg(&fe[p * U_ + lane]);
        a1 += w1 * v; a2 += w2 * v;
    }
    g_T1[((size_t)bh * NC8 + c8) * U_ + lane] = a1;
    g_T2[((size_t)bh * NC8 + c8) * U_ + lane] = a2;

    a1 = 0.f; a2 = 0.f;
#pragma unroll
    for (int i = 8; i < 16; i++) {
        const int jj = j0 + i;
        const int p = __ldg(&g_perm[bh * N_ + jj]);
        const float w1 = __ldg(&g_w1[bh * N_ + jj]);
        const float w2 = __ldg(&g_w2[bh * N_ + jj]);
        const float v = __ldg(&fe[p * U_ + lane]);
        a1 += w1 * v; a2 += w2 * v;
    }
    g_T1[((size_t)bh * NC8 + c8 + 1) * U_ + lane] = a1;
    g_T2[((size_t)bh * NC8 + c8 + 1) * U_ + lane] = a2;
}

// ============================================================
// k3b: exclusive scan of 512 chunk totals per (bh,u), 2-pass.
// warp w owns chunks [16w, 16w+16), lane -> u. grid BH, block 1024.
// ============================================================
__global__ void k3b_chunk_scan() {
    __shared__ float s1[32 * 32], s2[32 * 32];
    const int bh = blockIdx.x;
    const int w = threadIdx.x >> 5, lane = threadIdx.x & 31;

    // pass 1: warp totals
    float a1 = 0.f, a2 = 0.f;
#pragma unroll
    for (int i = 0; i < 16; i++) {
        const int ch = w * 16 + i;
        a1 += g_T1[((size_t)bh * NC8 + ch) * U_ + lane];
        a2 += g_T2[((size_t)bh * NC8 + ch) * U_ + lane];
    }
    s1[w * 32 + lane] = a1;
    s2[w * 32 + lane] = a2;
    __syncthreads();
    float off1 = 0.f, off2 = 0.f;
    for (int ww = 0; ww < w; ww++) {
        off1 += s1[ww * 32 + lane];
        off2 += s2[ww * 32 + lane];
    }
    // pass 2: write exclusive offsets
    float c1 = off1, c2 = off2;
#pragma unroll
    for (int i = 0; i < 16; i++) {
        const int ch = w * 16 + i;
        g_O1[((size_t)bh * NC8 + ch) * U_ + lane] = c1;
        g_O2[((size_t)bh * NC8 + ch) * U_ + lane] = c2;
        c1 += g_T1[((size_t)bh * NC8 + ch) * U_ + lane];
        c2 += g_T2[((size_t)bh * NC8 + ch) * U_ + lane];
    }
    if (w == 31) g_Ptot1[bh * U_ + lane] = off1 + a1;
}

// ============================================================
// k4: per-node combine. warp -> one n, lane -> u.
// Binary search, exclusive chunk offset, then <=8 row tail gather
// (feats rows are L2-resident; weights/perm are broadcast loads).
// grid BH*N/8, block 256
// ============================================================
__global__ void k4_output(const float* __restrict__ biases, float* __restrict__ out) {
    const int gw = blockIdx.x * 8 + (threadIdx.x >> 5);
    const int lane = threadIdx.x & 31;
    const int bh = gw >> 12;        // / N_
    const int n = gw & (N_ - 1);
    const int b = bh >> 2, h = bh & (H_ - 1);

    const float c = g_s[bh * N_ + n];
    const float th = -c;
    const float* ts = g_ts + bh * N_;

    int lo = 0, hi = N_;
    while (lo < hi) {
        const int mid = (lo + hi) >> 1;
        if (__ldg(&ts[mid]) < th) lo = mid + 1; else hi = mid;
    }
    const int k = lo;

    const float ea = expf(LEAKY * c);
    const float eb = expf(c);

    const float S1t = __ldg(&g_S1[bh * N_ + N_ - 1]);
    float S1ex = 0.f, S2ex = 0.f, p1 = 0.f, p2 = 0.f;
    if (k > 0) {
        const int km = k - 1;
        S1ex = __ldg(&g_S1[bh * N_ + km]);
        S2ex = __ldg(&g_S2[bh * N_ + km]);
        const int c8 = km >> 3;
        p1 = __ldg(&g_O1[((size_t)bh * NC8 + c8) * U_ + lane]);
        p2 = __ldg(&g_O2[((size_t)bh * NC8 + c8) * U_ + lane]);
        const float* fe = g_feats + (size_t)bh * N_ * U_;
        for (int j = c8 * 8; j <= km; j++) {
            const int p = __ldg(&g_perm[bh * N_ + j]);
            const float w1 = __ldg(&g_w1[bh * N_ + j]);
            const float w2 = __ldg(&g_w2[bh * N_ + j]);
            const float v = __ldg(&fe[p * U_ + lane]);
            p1 += w1 * v; p2 += w2 * v;
        }
    }
    const float pt1 = __ldg(&g_Ptot1[bh * U_ + lane]);

    const float Z = ea * S2ex + eb * (S1t - S1ex);
    const float num = ea * p2 + eb * (pt1 - p1);
    const float val = num / Z + __ldg(&biases[h * U_ + lane]);

    out[((size_t)b * N_ + n) * (H_ * U_) + h * U_ + lane] = fmaxf(val, 0.f);
}

// ============================================================
extern "C" void kernel_launch(void* const* d_in, const int* in_sizes, int n_in,
                              void* d_out, int out_size) {
    const float* x      = (const float*)d_in[0];
    const float* kern   = (const float*)d_in[1];
    const float* att_s  = (const float*)d_in[2];
    const float* att_n  = (const float*)d_in[3];
    const float* biases = (const float*)d_in[4];
    float* out = (float*)d_out;

    k1_feats<<<dim3(N_ / 128, BH_), 128>>>(x, kern, att_s, att_n);
    k2_sort_scan<<<BH_, 1024>>>();
    k3t_chunk_totals<<<dim3(BH_, 32), 256>>>();
    k3b_chunk_scan<<<BH_, 1024>>>();
    k4_output<<<(BH_ * N_) / 8, 256>>>(biases, out);
}

// round 7
// speedup vs baseline: 1.0457x; 1.0457x over previous
#include <cuda_runtime.h>
#include <cstdint>

#define LEAKY 0.2f
#define B_ 4
#define H_ 4
#define N_ 4096
#define F_ 64
#define U_ 32
#define BH_ (B_*H_)
#define NB_ 1024   // value-quantized bins per (b,h)

// ---------------- scratch (device globals; no allocations) ----------------
__device__ float g_feats[BH_ * N_ * U_];   // [bh][n][u]
__device__ float g_s[BH_ * N_];            // a_self (original order)
__device__ float g_t[BH_ * N_];            // a_neigh (original order)
__device__ float g_tso[BH_ * N_];          // t in bucket-scatter order
__device__ int   g_perm[BH_ * N_];         // scatter order -> original index
__device__ int   g_binstart[BH_ * (NB_ + 1)];
__device__ float g_lo[BH_], g_scale[BH_];
__device__ float g_T1[BH_ * NB_ * U_];     // per-bin sums of w1*feats
__device__ float g_T2[BH_ * NB_ * U_];     // per-bin sums of w2*feats
__device__ float g_O1[BH_ * NB_ * U_];     // exclusive bin offsets
__device__ float g_O2[BH_ * NB_ * U_];
__device__ float g_C1[BH_ * NB_];          // per-bin scalar sums of w1
__device__ float g_C2[BH_ * NB_];          // per-bin scalar sums of w2
__device__ float g_Sb1[BH_ * NB_];         // exclusive scalar offsets
__device__ float g_Sb2[BH_ * NB_];
__device__ float g_Stot1[BH_];             // total w1 scalar
__device__ float g_Ptot1[BH_ * U_];        // total w1*feats vector

// ============================================================
// k1: feats = x@K per head; s,t projections.
// grid (N/128, BH), block 128
// ============================================================
__global__ void __launch_bounds__(128) k1_feats(
        const float* __restrict__ x,
        const float* __restrict__ kern,
        const float* __restrict__ att_s,
        const float* __restrict__ att_n) {
    __shared__ float  xs[128][F_ + 1];
    __shared__ float4 ks4[F_ * (U_ / 4)];
    __shared__ float  as_s[U_], as_n[U_];

    const int bh = blockIdx.y;
    const int b = bh / H_, h = bh % H_;
    const int tid = threadIdx.x;

    const float4* ksrc = (const float4*)(kern + (size_t)h * F_ * U_);
    for (int i = tid; i < F_ * (U_ / 4); i += 128) ks4[i] = ksrc[i];
    if (tid < U_) { as_s[tid] = att_s[h * U_ + tid]; as_n[tid] = att_n[h * U_ + tid]; }

    const int n0 = blockIdx.x * 128;
    const float* xb = x + ((size_t)b * N_ + n0) * F_;
    for (int i = tid; i < 128 * F_; i += 128) xs[i >> 6][i & 63] = xb[i];
    __syncthreads();

    float acc[U_];
#pragma unroll
    for (int u = 0; u < U_; u++) acc[u] = 0.f;

#pragma unroll 4
    for (int f = 0; f < F_; f++) {
        const float xv = xs[tid][f];
#pragma unroll
        for (int u4 = 0; u4 < U_ / 4; u4++) {
            const float4 kv = ks4[f * (U_ / 4) + u4];
            acc[u4 * 4 + 0] += xv * kv.x;
            acc[u4 * 4 + 1] += xv * kv.y;
            acc[u4 * 4 + 2] += xv * kv.z;
            acc[u4 * 4 + 3] += xv * kv.w;
        }
    }

    const int n = n0 + tid;
    float* fo = g_feats + ((size_t)bh * N_ + n) * U_;
#pragma unroll
    for (int u4 = 0; u4 < U_ / 4; u4++) {
        ((float4*)fo)[u4] = make_float4(acc[u4*4], acc[u4*4+1], acc[u4*4+2], acc[u4*4+3]);
    }
    float s = 0.f, t = 0.f;
#pragma unroll
    for (int u = 0; u < U_; u++) { s += acc[u] * as_s[u]; t += acc[u] * as_n[u]; }
    g_s[bh * N_ + n] = s;
    g_t[bh * N_ + n] = t;
}

// ============================================================
// k2b: per-(b,h) value bucketing (replaces bitonic sort).
// block min/max of t -> monotone quantize to NB_ bins -> smem
// histogram -> exclusive scan -> scatter perm & t.
// grid BH, block 1024 (4 elements/thread)
// ============================================================
__global__ void __launch_bounds__(1024, 1) k2b_bucket() {
    __shared__ int   cnt[NB_];
    __shared__ float red[64];
    __shared__ int   wsum[32];
    __shared__ float slo, shi;

    const int bh = blockIdx.x;
    const int tid = threadIdx.x;
    const int lane = tid & 31, w = tid >> 5;

    float tv[4]; int bins[4];
    float mn = 1e30f, mx = -1e30f;
#pragma unroll
    for (int e = 0; e < 4; e++) {
        tv[e] = g_t[bh * N_ + tid * 4 + e];
        mn = fminf(mn, tv[e]); mx = fmaxf(mx, tv[e]);
    }
#pragma unroll
    for (int off = 16; off >= 1; off >>= 1) {
        mn = fminf(mn, __shfl_xor_sync(0xffffffffu, mn, off));
        mx = fmaxf(mx, __shfl_xor_sync(0xffffffffu, mx, off));
    }
    if (lane == 0) { red[w] = mn; red[32 + w] = mx; }
    cnt[tid] = 0;
    __syncthreads();
    if (w == 0) {
        float m1 = red[lane], m2 = red[32 + lane];
#pragma unroll
        for (int off = 16; off >= 1; off >>= 1) {
            m1 = fminf(m1, __shfl_xor_sync(0xffffffffu, m1, off));
            m2 = fmaxf(m2, __shfl_xor_sync(0xffffffffu, m2, off));
        }
        if (lane == 0) { slo = m1; shi = m2; }
    }
    __syncthreads();
    const float lo = slo;
    const float scale = (shi > lo) ? (float)NB_ * 0.999999f / (shi - lo) : 0.f;

#pragma unroll
    for (int e = 0; e < 4; e++) {
        int bi = (int)((tv[e] - lo) * scale);
        bi = min(NB_ - 1, max(0, bi));
        bins[e] = bi;
        atomicAdd(&cnt[bi], 1);
    }
    __syncthreads();

    // exclusive scan of cnt[NB_] (NB_ == blockDim)
    const int cval = cnt[tid];
    int inc = cval;
#pragma unroll
    for (int off = 1; off < 32; off <<= 1) {
        const int o = __shfl_up_sync(0xffffffffu, inc, off);
        if (lane >= off) inc += o;
    }
    if (lane == 31) wsum[w] = inc;
    __syncthreads();
    if (tid == 0) {
        int run = 0;
#pragma unroll
        for (int k = 0; k < 32; k++) { const int xk = wsum[k]; wsum[k] = run; run += xk; }
    }
    __syncthreads();
    const int ex = inc - cval + wsum[w];
    g_binstart[bh * (NB_ + 1) + tid] = ex;
    if (tid == 0) {
        g_binstart[bh * (NB_ + 1) + NB_] = N_;
        g_lo[bh] = lo; g_scale[bh] = scale;
    }
    cnt[tid] = ex;          // reuse as running offsets
    __syncthreads();

#pragma unroll
    for (int e = 0; e < 4; e++) {
        const int pos = atomicAdd(&cnt[bins[e]], 1);
        g_perm[bh * N_ + pos] = tid * 4 + e;
        g_tso[bh * N_ + pos]  = tv[e];
    }
}

// ============================================================
// k3: per-bin sums of w1*feats / w2*feats + scalar sums.
// grid (BH, NB/8), block 256 = 8 warps; warp -> bin, lane -> u.
// ============================================================
__global__ void __launch_bounds__(256) k3_bin_sums() {
    const int bh = blockIdx.x;
    const int w = threadIdx.x >> 5, lane = threadIdx.x & 31;
    const int bin = blockIdx.y * 8 + w;

    const int js = __ldg(&g_binstart[bh * (NB_ + 1) + bin]);
    const int je = __ldg(&g_binstart[bh * (NB_ + 1) + bin + 1]);
    const float* fe = g_feats + (size_t)bh * N_ * U_;

    float a1 = 0.f, a2 = 0.f, c1 = 0.f, c2 = 0.f;
    for (int j = js; j < je; j++) {
        const int p = __ldg(&g_perm[bh * N_ + j]);
        const float tv = __ldg(&g_tso[bh * N_ + j]);
        const float w1 = expf(tv);
        const float w2 = expf(LEAKY * tv);
        const float v = __ldg(&fe[p * U_ + lane]);
        a1 += w1 * v; a2 += w2 * v; c1 += w1; c2 += w2;
    }
    const size_t ti = ((size_t)bh * NB_ + bin) * U_ + lane;
    g_T1[ti] = a1;
    g_T2[ti] = a2;
    if (lane == 0) { g_C1[bh * NB_ + bin] = c1; g_C2[bh * NB_ + bin] = c2; }
}

// ============================================================
// k3b: exclusive scans over NB_ bins (vector per-u + scalars) + totals.
// grid BH, block 1024 = 32 warps; warp w owns bins [32w, 32w+32), lane -> u.
// __launch_bounds__(1024,1) keeps regs <= 64.
// ============================================================
__global__ void __launch_bounds__(1024, 1) k3b_scan() {
    __shared__ float s1[32 * 32], s2[32 * 32];
    const int bh = blockIdx.x;
    const int w = threadIdx.x >> 5, lane = threadIdx.x & 31;

    float a1 = 0.f, a2 = 0.f;
#pragma unroll 8
    for (int i = 0; i < 32; i++) {
        const size_t ti = ((size_t)bh * NB_ + w * 32 + i) * U_ + lane;
        a1 += g_T1[ti]; a2 += g_T2[ti];
    }
    s1[w * 32 + lane] = a1;
    s2[w * 32 + lane] = a2;
    __syncthreads();
    float off1 = 0.f, off2 = 0.f;
    for (int ww = 0; ww < w; ww++) {
        off1 += s1[ww * 32 + lane];
        off2 += s2[ww * 32 + lane];
    }
    float c1 = off1, c2 = off2;
#pragma unroll 8
    for (int i = 0; i < 32; i++) {
        const size_t ti = ((size_t)bh * NB_ + w * 32 + i) * U_ + lane;
        g_O1[ti] = c1; g_O2[ti] = c2;
        c1 += g_T1[ti]; c2 += g_T2[ti];
    }
    if (w == 31) g_Ptot1[bh * U_ + lane] = off1 + a1;

    __syncthreads();
    if (w == 0) {   // scalar scan: lane owns bins [32*lane, 32*lane+32)
        float b1 = 0.f, b2 = 0.f;
#pragma unroll 8
        for (int i = 0; i < 32; i++) {
            b1 += g_C1[bh * NB_ + lane * 32 + i];
            b2 += g_C2[bh * NB_ + lane * 32 + i];
        }
        float i1 = b1, i2 = b2;
#pragma unroll
        for (int off = 1; off < 32; off <<= 1) {
            const float x1 = __shfl_up_sync(0xffffffffu, i1, off);
            const float x2 = __shfl_up_sync(0xffffffffu, i2, off);
            if (lane >= off) { i1 += x1; i2 += x2; }
        }
        float r1 = i1 - b1, r2 = i2 - b2;
#pragma unroll 8
        for (int i = 0; i < 32; i++) {
            const int ch = bh * NB_ + lane * 32 + i;
            g_Sb1[ch] = r1; g_Sb2[ch] = r2;
            r1 += g_C1[ch]; r2 += g_C2[ch];
        }
        if (lane == 31) g_Stot1[bh] = i1;
    }
}

// ============================================================
// k4: per-node combine. warp -> one n, lane -> u.
// Bin lookup (one FMA, no binary search), exclusive bin offsets,
// then exact boundary-bin loop (avg ~4, max ~tens of L2-hit rows).
// grid BH*N/8, block 256
// ============================================================
__global__ void __launch_bounds__(256) k4_output(
        const float* __restrict__ biases, float* __restrict__ out) {
    const int gw = blockIdx.x * 8 + (threadIdx.x >> 5);
    const int lane = threadIdx.x & 31;
    const int bh = gw >> 12;        // / N_
    const int n = gw & (N_ - 1);
    const int b = bh >> 2, h = bh & (H_ - 1);

    const float c = g_s[bh * N_ + n];
    const float th = -c;
    const float lo = __ldg(&g_lo[bh]);
    const float scale = __ldg(&g_scale[bh]);
    int bq = (int)((th - lo) * scale);
    bq = min(NB_ - 1, max(0, bq));

    float p1 = __ldg(&g_O1[((size_t)bh * NB_ + bq) * U_ + lane]);
    float p2 = __ldg(&g_O2[((size_t)bh * NB_ + bq) * U_ + lane]);
    float s1 = __ldg(&g_Sb1[bh * NB_ + bq]);
    float s2 = __ldg(&g_Sb2[bh * NB_ + bq]);

    const int js = __ldg(&g_binstart[bh * (NB_ + 1) + bq]);
    const int je = __ldg(&g_binstart[bh * (NB_ + 1) + bq + 1]);
    const float* fe = g_feats + (size_t)bh * N_ * U_;
    for (int j = js; j < je; j++) {
        const float tv = __ldg(&g_tso[bh * N_ + j]);
        if (tv < th) {
            const float w1 = expf(tv);
            const float w2 = expf(LEAKY * tv);
            const int p = __ldg(&g_perm[bh * N_ + j]);
            const float v = __ldg(&fe[p * U_ + lane]);
            p1 += w1 * v; p2 += w2 * v; s1 += w1; s2 += w2;
        }
    }

    const float ea = expf(LEAKY * c);
    const float eb = expf(c);
    const float S1t = __ldg(&g_Stot1[bh]);
    const float pt1 = __ldg(&g_Ptot1[bh * U_ + lane]);

    const float Z = ea * s2 + eb * (S1t - s1);
    const float num = ea * p2 + eb * (pt1 - p1);
    const float val = num / Z + __ldg(&biases[h * U_ + lane]);

    out[((size_t)b * N_ + n) * (H_ * U_) + h * U_ + lane] = fmaxf(val, 0.f);
}

// ============================================================
extern "C" void kernel_launch(void* const* d_in, const int* in_sizes, int n_in,
                              void* d_out, int out_size) {
    const float* x      = (const float*)d_in[0];
    const float* kern   = (const float*)d_in[1];
    const float* att_s  = (const float*)d_in[2];
    const float* att_n  = (const float*)d_in[3];
    const float* biases = (const float*)d_in[4];
    float* out = (float*)d_out;

    k1_feats<<<dim3(N_ / 128, BH_), 128>>>(x, kern, att_s, att_n);
    k2b_bucket<<<BH_, 1024>>>();
    k3_bin_sums<<<dim3(BH_, NB_ / 8), 256>>>();
    k3b_scan<<<BH_, 1024>>>();
    k4_output<<<(BH_ * N_) / 8, 256>>>(biases, out);
}

// round 8
// speedup vs baseline: 1.0996x; 1.0515x over previous
#include <cuda_runtime.h>
#include <cstdint>

#define LEAKY 0.2f
#define B_ 4
#define H_ 4
#define N_ 4096
#define F_ 64
#define U_ 32
#define BH_ (B_*H_)
#define NB_ 1024   // value-quantized bins per (b,h)

// ---------------- scratch (device globals; no allocations) ----------------
__device__ float g_feats[BH_ * N_ * U_];   // [bh][n][u]
__device__ float g_s[BH_ * N_];            // a_self (original order)
__device__ float g_t[BH_ * N_];            // a_neigh (original order)
__device__ float g_tso[BH_ * N_];          // t in bucket-scatter order
__device__ int   g_perm[BH_ * N_];         // scatter order -> original index
__device__ int   g_binstart[BH_ * (NB_ + 1)];
__device__ float g_lo[BH_], g_scale[BH_];
__device__ float g_T1t[BH_ * U_ * NB_];    // per-bin sums of w1*feats, TRANSPOSED [bh][u][bin]
__device__ float g_T2t[BH_ * U_ * NB_];    // per-bin sums of w2*feats, TRANSPOSED
__device__ float g_O1[BH_ * NB_ * U_];     // exclusive bin offsets [bh][bin][u]
__device__ float g_O2[BH_ * NB_ * U_];
__device__ float g_C1[BH_ * NB_];          // per-bin scalar sums of w1
__device__ float g_C2[BH_ * NB_];          // per-bin scalar sums of w2
__device__ float g_Sb1[BH_ * NB_];         // exclusive scalar offsets
__device__ float g_Sb2[BH_ * NB_];
__device__ float g_Stot1[BH_];             // total w1 scalar
__device__ float g_Ptot1[BH_ * U_];        // total w1*feats vector

// ============================================================
// k1: feats = x@K per head; s,t projections.
// grid (N/128, BH), block 128
// ============================================================
__global__ void __launch_bounds__(128) k1_feats(
        const float* __restrict__ x,
        const float* __restrict__ kern,
        const float* __restrict__ att_s,
        const float* __restrict__ att_n) {
    __shared__ float  xs[128][F_ + 1];
    __shared__ float4 ks4[F_ * (U_ / 4)];
    __shared__ float  as_s[U_], as_n[U_];

    const int bh = blockIdx.y;
    const int b = bh / H_, h = bh % H_;
    const int tid = threadIdx.x;

    const float4* ksrc = (const float4*)(kern + (size_t)h * F_ * U_);
    for (int i = tid; i < F_ * (U_ / 4); i += 128) ks4[i] = ksrc[i];
    if (tid < U_) { as_s[tid] = att_s[h * U_ + tid]; as_n[tid] = att_n[h * U_ + tid]; }

    const int n0 = blockIdx.x * 128;
    const float* xb = x + ((size_t)b * N_ + n0) * F_;
    for (int i = tid; i < 128 * F_; i += 128) xs[i >> 6][i & 63] = xb[i];
    __syncthreads();

    float acc[U_];
#pragma unroll
    for (int u = 0; u < U_; u++) acc[u] = 0.f;

#pragma unroll 4
    for (int f = 0; f < F_; f++) {
        const float xv = xs[tid][f];
#pragma unroll
        for (int u4 = 0; u4 < U_ / 4; u4++) {
            const float4 kv = ks4[f * (U_ / 4) + u4];
            acc[u4 * 4 + 0] += xv * kv.x;
            acc[u4 * 4 + 1] += xv * kv.y;
            acc[u4 * 4 + 2] += xv * kv.z;
            acc[u4 * 4 + 3] += xv * kv.w;
        }
    }

    const int n = n0 + tid;
    float* fo = g_feats + ((size_t)bh * N_ + n) * U_;
#pragma unroll
    for (int u4 = 0; u4 < U_ / 4; u4++) {
        ((float4*)fo)[u4] = make_float4(acc[u4*4], acc[u4*4+1], acc[u4*4+2], acc[u4*4+3]);
    }
    float s = 0.f, t = 0.f;
#pragma unroll
    for (int u = 0; u < U_; u++) { s += acc[u] * as_s[u]; t += acc[u] * as_n[u]; }
    g_s[bh * N_ + n] = s;
    g_t[bh * N_ + n] = t;
}

// ============================================================
// k2b: per-(b,h) value bucketing.
// grid BH, block 1024 (4 elements/thread)
// ============================================================
__global__ void __launch_bounds__(1024, 1) k2b_bucket() {
    __shared__ int   cnt[NB_];
    __shared__ float red[64];
    __shared__ int   wsum[32];
    __shared__ float slo, shi;

    const int bh = blockIdx.x;
    const int tid = threadIdx.x;
    const int lane = tid & 31, w = tid >> 5;

    float tv[4]; int bins[4];
    float mn = 1e30f, mx = -1e30f;
#pragma unroll
    for (int e = 0; e < 4; e++) {
        tv[e] = g_t[bh * N_ + tid * 4 + e];
        mn = fminf(mn, tv[e]); mx = fmaxf(mx, tv[e]);
    }
#pragma unroll
    for (int off = 16; off >= 1; off >>= 1) {
        mn = fminf(mn, __shfl_xor_sync(0xffffffffu, mn, off));
        mx = fmaxf(mx, __shfl_xor_sync(0xffffffffu, mx, off));
    }
    if (lane == 0) { red[w] = mn; red[32 + w] = mx; }
    cnt[tid] = 0;
    __syncthreads();
    if (w == 0) {
        float m1 = red[lane], m2 = red[32 + lane];
#pragma unroll
        for (int off = 16; off >= 1; off >>= 1) {
            m1 = fminf(m1, __shfl_xor_sync(0xffffffffu, m1, off));
            m2 = fmaxf(m2, __shfl_xor_sync(0xffffffffu, m2, off));
        }
        if (lane == 0) { slo = m1; shi = m2; }
    }
    __syncthreads();
    const float lo = slo;
    const float scale = (shi > lo) ? (float)NB_ * 0.999999f / (shi - lo) : 0.f;

#pragma unroll
    for (int e = 0; e < 4; e++) {
        int bi = (int)((tv[e] - lo) * scale);
        bi = min(NB_ - 1, max(0, bi));
        bins[e] = bi;
        atomicAdd(&cnt[bi], 1);
    }
    __syncthreads();

    // exclusive scan of cnt[NB_]
    const int cval = cnt[tid];
    int inc = cval;
#pragma unroll
    for (int off = 1; off < 32; off <<= 1) {
        const int o = __shfl_up_sync(0xffffffffu, inc, off);
        if (lane >= off) inc += o;
    }
    if (lane == 31) wsum[w] = inc;
    __syncthreads();
    if (tid == 0) {
        int run = 0;
#pragma unroll
        for (int k = 0; k < 32; k++) { const int xk = wsum[k]; wsum[k] = run; run += xk; }
    }
    __syncthreads();
    const int ex = inc - cval + wsum[w];
    g_binstart[bh * (NB_ + 1) + tid] = ex;
    if (tid == 0) {
        g_binstart[bh * (NB_ + 1) + NB_] = N_;
        g_lo[bh] = lo; g_scale[bh] = scale;
    }
    cnt[tid] = ex;          // reuse as running offsets
    __syncthreads();

#pragma unroll
    for (int e = 0; e < 4; e++) {
        const int pos = atomicAdd(&cnt[bins[e]], 1);
        g_perm[bh * N_ + pos] = tid * 4 + e;
        g_tso[bh * N_ + pos]  = tv[e];
    }
}

// ============================================================
// k3: per-bin sums of w1*feats / w2*feats + scalar sums.
// Writes vector totals TRANSPOSED [bh][u][bin] so k3b's scan
// reads are contiguous. Scattered stores are fire-and-forget.
// grid (BH, NB/8), block 256 = 8 warps; warp -> bin, lane -> u.
// ============================================================
__global__ void __launch_bounds__(256) k3_bin_sums() {
    const int bh = blockIdx.x;
    const int w = threadIdx.x >> 5, lane = threadIdx.x & 31;
    const int bin = blockIdx.y * 8 + w;

    const int js = __ldg(&g_binstart[bh * (NB_ + 1) + bin]);
    const int je = __ldg(&g_binstart[bh * (NB_ + 1) + bin + 1]);
    const float* fe = g_feats + (size_t)bh * N_ * U_;

    float a1 = 0.f, a2 = 0.f, c1 = 0.f, c2 = 0.f;
    for (int j = js; j < je; j++) {
        const int p = __ldg(&g_perm[bh * N_ + j]);
        const float tv = __ldg(&g_tso[bh * N_ + j]);
        const float w1 = expf(tv);
        const float w2 = expf(LEAKY * tv);
        const float v = __ldg(&fe[p * U_ + lane]);
        a1 += w1 * v; a2 += w2 * v; c1 += w1; c2 += w2;
    }
    const size_t ti = ((size_t)bh * U_ + lane) * NB_ + bin;   // transposed
    g_T1t[ti] = a1;
    g_T2t[ti] = a2;
    if (lane == 0) { g_C1[bh * NB_ + bin] = c1; g_C2[bh * NB_ + bin] = c2; }
}

// ============================================================
// dual exclusive scan of two contiguous 1024-float rows.
// block = 256 threads, 4 elements/thread via float4.
// out index = bin * ostride (caller pre-offsets base).
// ============================================================
__device__ __forceinline__ void dual_scan_1024(
        const float* __restrict__ in1, const float* __restrict__ in2,
        float* __restrict__ out1, float* __restrict__ out2, int ostride,
        float* __restrict__ tot1) {
    __shared__ float ws1[8], ws2[8];
    const int tid = threadIdx.x, lane = tid & 31, w = tid >> 5;

    const float4 a = ((const float4*)in1)[tid];
    const float4 b = ((const float4*)in2)[tid];
    float l1[4], l2[4];
    l1[0] = a.x; l1[1] = l1[0] + a.y; l1[2] = l1[1] + a.z; l1[3] = l1[2] + a.w;
    l2[0] = b.x; l2[1] = l2[0] + b.y; l2[2] = l2[1] + b.z; l2[3] = l2[2] + b.w;
    const float t1 = l1[3], t2 = l2[3];
    float i1 = t1, i2 = t2;
#pragma unroll
    for (int off = 1; off < 32; off <<= 1) {
        const float x1 = __shfl_up_sync(0xffffffffu, i1, off);
        const float x2 = __shfl_up_sync(0xffffffffu, i2, off);
        if (lane >= off) { i1 += x1; i2 += x2; }
    }
    if (lane == 31) { ws1[w] = i1; ws2[w] = i2; }
    __syncthreads();
    float off1 = 0.f, off2 = 0.f;
#pragma unroll
    for (int k = 0; k < 8; k++) {
        if (k < w) { off1 += ws1[k]; off2 += ws2[k]; }
    }
    const float e1 = off1 + i1 - t1;   // exclusive start for this thread
    const float e2 = off2 + i2 - t2;
    const int base = 4 * tid;
    out1[(base + 0) * ostride] = e1;
    out1[(base + 1) * ostride] = e1 + l1[0];
    out1[(base + 2) * ostride] = e1 + l1[1];
    out1[(base + 3) * ostride] = e1 + l1[2];
    out2[(base + 0) * ostride] = e2;
    out2[(base + 1) * ostride] = e2 + l2[0];
    out2[(base + 2) * ostride] = e2 + l2[1];
    out2[(base + 3) * ostride] = e2 + l2[2];
    if (tot1 && tid == 255) *tot1 = off1 + i1;   // grand total of array 1
}

// ============================================================
// k3b v2: grid = BH*33, block 256.
// r<32: exclusive scan of T1t/T2t row (bh,u) -> O1/O2 [bh][bin][u] + Ptot1.
// r==32: scalar scans C1->Sb1 (+Stot1), C2->Sb2.
// ============================================================
__global__ void __launch_bounds__(256) k3b_scan() {
    const int bh = blockIdx.x / 33;
    const int r  = blockIdx.x % 33;

    if (r < 32) {
        const size_t bi = ((size_t)bh * U_ + r) * NB_;
        dual_scan_1024(g_T1t + bi, g_T2t + bi,
                       g_O1 + (size_t)bh * NB_ * U_ + r,
                       g_O2 + (size_t)bh * NB_ * U_ + r,
                       U_,
                       &g_Ptot1[bh * U_ + r]);
    } else {
        dual_scan_1024(g_C1 + bh * NB_, g_C2 + bh * NB_,
                       g_Sb1 + bh * NB_, g_Sb2 + bh * NB_, 1,
                       &g_Stot1[bh]);
    }
}

// ============================================================
// k4: per-node combine. warp -> one n, lane -> u.
// grid BH*N/8, block 256
// ============================================================
__global__ void __launch_bounds__(256) k4_output(
        const float* __restrict__ biases, float* __restrict__ out) {
    const int gw = blockIdx.x * 8 + (threadIdx.x >> 5);
    const int lane = threadIdx.x & 31;
    const int bh = gw >> 12;        // / N_
    const int n = gw & (N_ - 1);
    const int b = bh >> 2, h = bh & (H_ - 1);

    const float c = g_s[bh * N_ + n];
    const float th = -c;
    const float lo = __ldg(&g_lo[bh]);
    const float scale = __ldg(&g_scale[bh]);
    int bq = (int)((th - lo) * scale);
    bq = min(NB_ - 1, max(0, bq));

    float p1 = __ldg(&g_O1[((size_t)bh * NB_ + bq) * U_ + lane]);
    float p2 = __ldg(&g_O2[((size_t)bh * NB_ + bq) * U_ + lane]);
    float s1 = __ldg(&g_Sb1[bh * NB_ + bq]);
    float s2 = __ldg(&g_Sb2[bh * NB_ + bq]);

    const int js = __ldg(&g_binstart[bh * (NB_ + 1) + bq]);
    const int je = __ldg(&g_binstart[bh * (NB_ + 1) + bq + 1]);
    const float* fe = g_feats + (size_t)bh * N_ * U_;
    for (int j = js; j < je; j++) {
        const float tv = __ldg(&g_tso[bh * N_ + j]);
        if (tv < th) {
            const float w1 = expf(tv);
            const float w2 = expf(LEAKY * tv);
            const int p = __ldg(&g_perm[bh * N_ + j]);
            const float v = __ldg(&fe[p * U_ + lane]);
            p1 += w1 * v; p2 += w2 * v; s1 += w1; s2 += w2;
        }
    }

    const float ea = expf(LEAKY * c);
    const float eb = expf(c);
    const float S1t = __ldg(&g_Stot1[bh]);
    const float pt1 = __ldg(&g_Ptot1[bh * U_ + lane]);

    const float Z = ea * s2 + eb * (S1t - s1);
    const float num = ea * p2 + eb * (pt1 - p1);
    const float val = num / Z + __ldg(&biases[h * U_ + lane]);

    out[((size_t)b * N_ + n) * (H_ * U_) + h * U_ + lane] = fmaxf(val, 0.f);
}

// ============================================================
extern "C" void kernel_launch(void* const* d_in, const int* in_sizes, int n_in,
                              void* d_out, int out_size) {
    const float* x      = (const float*)d_in[0];
    const float* kern   = (const float*)d_in[1];
    const float* att_s  = (const float*)d_in[2];
    const float* att_n  = (const float*)d_in[3];
    const float* biases = (const float*)d_in[4];
    float* out = (float*)d_out;

    k1_feats<<<dim3(N_ / 128, BH_), 128>>>(x, kern, att_s, att_n);
    k2b_bucket<<<BH_, 1024>>>();
    k3_bin_sums<<<dim3(BH_, NB_ / 8), 256>>>();
    k3b_scan<<<BH_ * 33, 256>>>();
    k4_output<<<(BH_ * N_) / 8, 256>>>(biases, out);
}